// round 1
// baseline (speedup 1.0000x reference)
#include <cuda_runtime.h>
#include <cstdint>

#define DD 128
#define NPAD 50048            // 391 * 128, covers N=50000
#define GMAXC 64

// ---- scratch (device globals; no allocation allowed) ----
__device__ float g_Xd[(size_t)NPAD * DD];
__device__ float g_Xc[(size_t)NPAD * DD];
__device__ float g_aggA[(size_t)NPAD * DD];
__device__ float g_aggB[(size_t)NPAD * DD];
__device__ float g_cnt[GMAXC];

// ============================================================
// GEMM: out = op(Xin) @ W[layer] + b[layer]
// blockIdx.y selects family: 0 -> (Wd,bd)->g_Xd, 1 -> (Wc,bc)->g_Xc,
//                            2 -> (Ws,bs)-> agg buffer (self-term init)
// BM=128, BN=128(full D), BK=16, 256 threads, 8x8 per-thread tile.
// relu_in applies ReLU on the input load (fused activation of prev layer).
// ============================================================
__global__ __launch_bounds__(256) void gemm3_kernel(
    const float* __restrict__ Xext, int in_sel, int relu_in,
    const float* __restrict__ Wd, const float* __restrict__ bd,
    const float* __restrict__ Wc, const float* __restrict__ bc,
    const float* __restrict__ Ws, const float* __restrict__ bs,
    int layer, int out_agg, int N)
{
    const float* Xin = (in_sel == 0) ? Xext : (in_sel == 1 ? g_aggA : g_aggB);
    const float* W; const float* bias; float* out;
    if (blockIdx.y == 0)      { W = Wd; bias = bd; out = g_Xd; }
    else if (blockIdx.y == 1) { W = Wc; bias = bc; out = g_Xc; }
    else                      { W = Ws; bias = bs; out = (out_agg == 0 ? g_aggA : g_aggB); }
    W    += (size_t)layer * DD * DD;
    bias += layer * DD;

    __shared__ float As[16][132];   // A transposed: As[k][m]
    __shared__ float Bs[16][132];   // Bs[k][n]

    const int tid = threadIdx.x;
    const int tx  = tid & 15;       // col group (8 cols each)
    const int ty  = tid >> 4;       // row group (8 rows each)
    const int row0 = blockIdx.x * 128;

    float acc[8][8];
#pragma unroll
    for (int i = 0; i < 8; i++)
#pragma unroll
        for (int j = 0; j < 8; j++) acc[i][j] = 0.f;

    for (int k0 = 0; k0 < DD; k0 += 16) {
        // load A tile 128x16 (transposed into As)
#pragma unroll
        for (int q = 0; q < 2; q++) {
            int f = tid * 2 + q;          // float4 index 0..511
            int r = f >> 2;               // row 0..127
            int c = (f & 3) << 2;         // col 0,4,8,12
            int gr = row0 + r;
            float4 v = make_float4(0.f, 0.f, 0.f, 0.f);
            if (gr < N)
                v = *(const float4*)(Xin + (size_t)gr * DD + k0 + c);
            if (relu_in) {
                v.x = fmaxf(v.x, 0.f); v.y = fmaxf(v.y, 0.f);
                v.z = fmaxf(v.z, 0.f); v.w = fmaxf(v.w, 0.f);
            }
            As[c + 0][r] = v.x; As[c + 1][r] = v.y;
            As[c + 2][r] = v.z; As[c + 3][r] = v.w;
        }
        // load B tile 16x128
#pragma unroll
        for (int q = 0; q < 2; q++) {
            int f = tid * 2 + q;
            int r = f >> 5;               // row 0..15
            int c = (f & 31) << 2;        // col 0..124 step 4
            float4 v = *(const float4*)(W + (size_t)(k0 + r) * DD + c);
            Bs[r][c + 0] = v.x; Bs[r][c + 1] = v.y;
            Bs[r][c + 2] = v.z; Bs[r][c + 3] = v.w;
        }
        __syncthreads();

#pragma unroll
        for (int kk = 0; kk < 16; kk++) {
            float a[8], b[8];
#pragma unroll
            for (int i = 0; i < 8; i++) a[i] = As[kk][ty * 8 + i];
#pragma unroll
            for (int j = 0; j < 8; j++) b[j] = Bs[kk][tx * 8 + j];
#pragma unroll
            for (int i = 0; i < 8; i++)
#pragma unroll
                for (int j = 0; j < 8; j++)
                    acc[i][j] = fmaf(a[i], b[j], acc[i][j]);
        }
        __syncthreads();
    }

    // epilogue: +bias, vectorized stores
    float bv[8];
#pragma unroll
    for (int j = 0; j < 8; j++) bv[j] = bias[tx * 8 + j];

#pragma unroll
    for (int i = 0; i < 8; i++) {
        int gr = row0 + ty * 8 + i;
        if (gr >= N) continue;
        float4 s0, s1;
        s0.x = acc[i][0] + bv[0]; s0.y = acc[i][1] + bv[1];
        s0.z = acc[i][2] + bv[2]; s0.w = acc[i][3] + bv[3];
        s1.x = acc[i][4] + bv[4]; s1.y = acc[i][5] + bv[5];
        s1.z = acc[i][6] + bv[6]; s1.w = acc[i][7] + bv[7];
        float* op = out + (size_t)gr * DD + tx * 8;
        *(float4*)(op)     = s0;
        *(float4*)(op + 4) = s1;
    }
}

// ============================================================
// Edge scatter: one warp per edge. Lane l handles floats [4l,4l+4).
// msg = (type==0 ? Xd : Xc)[src]; agg[dst] += msg via red.global.add.v4.f32
// ============================================================
__global__ __launch_bounds__(256) void edge_kernel(
    const int* __restrict__ ei, const int* __restrict__ et,
    int E, int agg_sel)
{
    int warp = blockIdx.x * 8 + (threadIdx.x >> 5);
    int lane = threadIdx.x & 31;
    if (warp >= E) return;

    int src = ei[warp];
    int dst = ei[E + warp];
    int t   = et[warp];

    const float* sp = ((t == 0) ? g_Xd : g_Xc) + (size_t)src * DD + lane * 4;
    float4 v = *(const float4*)sp;

    float* agg = (agg_sel == 0) ? g_aggA : g_aggB;
    float* dp = agg + (size_t)dst * DD + lane * 4;
    asm volatile("red.global.add.v4.f32 [%0], {%1,%2,%3,%4};"
                 :: "l"(dp), "f"(v.x), "f"(v.y), "f"(v.z), "f"(v.w)
                 : "memory");
}

// ============================================================
// Pooling
// ============================================================
__global__ void zero_kernel(float* __restrict__ out, int out_size, int G)
{
    int i = blockIdx.x * blockDim.x + threadIdx.x;
    if (i < out_size) out[i] = 0.f;
    if (i < G) g_cnt[i] = 0.f;
}

// one warp per node: relu(final agg) accumulated into out[batch_id]
__global__ __launch_bounds__(256) void pool_accum_kernel(
    const int* __restrict__ batch_ids, float* __restrict__ out,
    int N, int agg_sel)
{
    int node = blockIdx.x * 8 + (threadIdx.x >> 5);
    int lane = threadIdx.x & 31;
    if (node >= N) return;

    int b = batch_ids[node];
    const float* agg = (agg_sel == 0) ? g_aggA : g_aggB;
    const float* sp = agg + (size_t)node * DD + lane * 4;
    float4 v = *(const float4*)sp;
    v.x = fmaxf(v.x, 0.f); v.y = fmaxf(v.y, 0.f);
    v.z = fmaxf(v.z, 0.f); v.w = fmaxf(v.w, 0.f);

    float* dp = out + (size_t)b * DD + lane * 4;
    asm volatile("red.global.add.v4.f32 [%0], {%1,%2,%3,%4};"
                 :: "l"(dp), "f"(v.x), "f"(v.y), "f"(v.z), "f"(v.w)
                 : "memory");
    if (lane == 0)
        atomicAdd(&g_cnt[b], 1.0f);
}

__global__ void pool_div_kernel(float* __restrict__ out, int out_size)
{
    int i = blockIdx.x * blockDim.x + threadIdx.x;
    if (i >= out_size) return;
    out[i] = out[i] / fmaxf(g_cnt[i >> 7], 1.0f);
}

// ============================================================
// launch
// ============================================================
extern "C" void kernel_launch(void* const* d_in, const int* in_sizes, int n_in,
                              void* d_out, int out_size)
{
    const float* X   = (const float*)d_in[0];
    const float* Wd  = (const float*)d_in[1];
    const float* bd  = (const float*)d_in[2];
    const float* Wc  = (const float*)d_in[3];
    const float* bc  = (const float*)d_in[4];
    const float* Ws  = (const float*)d_in[5];
    const float* bs  = (const float*)d_in[6];
    const int*   ei  = (const int*)d_in[7];
    const int*   et  = (const int*)d_in[8];
    const int*   bid = (const int*)d_in[9];
    float* out = (float*)d_out;

    const int N = in_sizes[0] / DD;
    const int E = in_sizes[8];
    const int G = out_size / DD;

    dim3 ggrid((N + 127) / 128, 3);
    int eblocks = (E + 7) / 8;
    int nblocks = (N + 7) / 8;

    // layer 0: input X (no relu) -> Xd/Xc, self-term -> aggA; edges add into aggA
    gemm3_kernel<<<ggrid, 256>>>(X, 0, 0, Wd, bd, Wc, bc, Ws, bs, 0, 0, N);
    edge_kernel<<<eblocks, 256>>>(ei, et, E, 0);

    // layer 1: input relu(aggA) -> Xd/Xc, self-term -> aggB; edges add into aggB
    gemm3_kernel<<<ggrid, 256>>>(X, 1, 1, Wd, bd, Wc, bc, Ws, bs, 1, 1, N);
    edge_kernel<<<eblocks, 256>>>(ei, et, E, 1);

    // layer 2: input relu(aggB) -> Xd/Xc, self-term -> aggA; edges add into aggA
    gemm3_kernel<<<ggrid, 256>>>(X, 2, 1, Wd, bd, Wc, bc, Ws, bs, 2, 0, N);
    edge_kernel<<<eblocks, 256>>>(ei, et, E, 0);

    // pool: mean over relu(aggA) per graph
    zero_kernel<<<(out_size + G + 255) / 256, 256>>>(out, out_size, G);
    pool_accum_kernel<<<nblocks, 256>>>(bid, out, N, 0);
    pool_div_kernel<<<(out_size + 255) / 256, 256>>>(out, out_size);
}

// round 2
// speedup vs baseline: 1.1730x; 1.1730x over previous
#include <cuda_runtime.h>
#include <cstdint>

#define DD 128
#define NPAD 50048            // 391 * 128, covers N=50000
#define GMAXC 64

// ---- scratch (device globals; no allocation allowed) ----
__device__ float g_Xd[(size_t)NPAD * DD];
__device__ float g_Xc[(size_t)NPAD * DD];
__device__ float g_aggA[(size_t)NPAD * DD];
__device__ float g_aggB[(size_t)NPAD * DD];
__device__ float g_cnt[GMAXC];

// packed fp32x2 FMA (Blackwell): d = a*b + d, two lanes per instruction
#define FMA_F32X2(d, a, b) \
    asm("fma.rn.f32x2 %0, %1, %2, %0;" : "+l"(d) : "l"(a), "l"(b))
#define SPLAT2(out, x) \
    asm("mov.b64 %0, {%1, %1};" : "=l"(out) : "f"(x))

// ============================================================
// GEMM: out = op(Xin) @ W[layer] + b[layer]
// blockIdx.y selects family: 0 -> (Wd,bd)->g_Xd, 1 -> (Wc,bc)->g_Xc,
//                            2 -> (Ws,bs)-> agg buffer (self-term init)
// BM=128, BN=128(full D), BK=16, 256 threads, 8x8 per-thread tile,
// accumulators packed in f32x2 pairs along the row dim.
// ============================================================
__global__ __launch_bounds__(256) void gemm3_kernel(
    const float* __restrict__ Xext, int in_sel, int relu_in,
    const float* __restrict__ Wd, const float* __restrict__ bd,
    const float* __restrict__ Wc, const float* __restrict__ bc,
    const float* __restrict__ Ws, const float* __restrict__ bs,
    int layer, int out_agg, int N)
{
    const float* Xin = (in_sel == 0) ? Xext : (in_sel == 1 ? g_aggA : g_aggB);
    const float* W; const float* bias; float* out;
    if (blockIdx.y == 0)      { W = Wd; bias = bd; out = g_Xd; }
    else if (blockIdx.y == 1) { W = Wc; bias = bc; out = g_Xc; }
    else                      { W = Ws; bias = bs; out = (out_agg == 0 ? g_aggA : g_aggB); }
    W    += (size_t)layer * DD * DD;
    bias += layer * DD;

    __shared__ float As[16][132];   // A transposed: As[k][m]  (132: 16B-aligned rows, pad vs conflicts)
    __shared__ float Bs[16][132];   // Bs[k][n]

    const int tid = threadIdx.x;
    const int tx  = tid & 15;       // col group (8 cols each)
    const int ty  = tid >> 4;       // row group (8 rows each)
    const int row0 = blockIdx.x * 128;

    // acc2[i2][j] packs rows (2*i2, 2*i2+1) for column j
    unsigned long long acc2[4][8];
#pragma unroll
    for (int i = 0; i < 4; i++)
#pragma unroll
        for (int j = 0; j < 8; j++) acc2[i][j] = 0ull;

    for (int k0 = 0; k0 < DD; k0 += 16) {
        // load A tile 128x16 (transposed into As)
#pragma unroll
        for (int q = 0; q < 2; q++) {
            int f = tid * 2 + q;          // float4 index 0..511
            int r = f >> 2;               // row 0..127
            int c = (f & 3) << 2;         // col 0,4,8,12
            int gr = row0 + r;
            float4 v = make_float4(0.f, 0.f, 0.f, 0.f);
            if (gr < N)
                v = *(const float4*)(Xin + (size_t)gr * DD + k0 + c);
            if (relu_in) {
                v.x = fmaxf(v.x, 0.f); v.y = fmaxf(v.y, 0.f);
                v.z = fmaxf(v.z, 0.f); v.w = fmaxf(v.w, 0.f);
            }
            As[c + 0][r] = v.x; As[c + 1][r] = v.y;
            As[c + 2][r] = v.z; As[c + 3][r] = v.w;
        }
        // load B tile 16x128
#pragma unroll
        for (int q = 0; q < 2; q++) {
            int f = tid * 2 + q;
            int r = f >> 5;               // row 0..15
            int c = (f & 31) << 2;        // col 0..124 step 4
            float4 v = *(const float4*)(W + (size_t)(k0 + r) * DD + c);
            Bs[r][c + 0] = v.x; Bs[r][c + 1] = v.y;
            Bs[r][c + 2] = v.z; Bs[r][c + 3] = v.w;
        }
        __syncthreads();

#pragma unroll
        for (int kk = 0; kk < 16; kk++) {
            // A pairs load directly as 8B words (rows contiguous in As)
            ulonglong2 a01 = *(const ulonglong2*)&As[kk][ty * 8];
            ulonglong2 a23 = *(const ulonglong2*)&As[kk][ty * 8 + 4];
            unsigned long long a2[4] = {a01.x, a01.y, a23.x, a23.y};
            float4 bA = *(const float4*)&Bs[kk][tx * 8];
            float4 bB = *(const float4*)&Bs[kk][tx * 8 + 4];
            unsigned long long b2[8];
            SPLAT2(b2[0], bA.x); SPLAT2(b2[1], bA.y);
            SPLAT2(b2[2], bA.z); SPLAT2(b2[3], bA.w);
            SPLAT2(b2[4], bB.x); SPLAT2(b2[5], bB.y);
            SPLAT2(b2[6], bB.z); SPLAT2(b2[7], bB.w);
#pragma unroll
            for (int i = 0; i < 4; i++)
#pragma unroll
                for (int j = 0; j < 8; j++)
                    FMA_F32X2(acc2[i][j], a2[i], b2[j]);
        }
        __syncthreads();
    }

    // epilogue: +bias, vectorized stores
    float bv[8];
#pragma unroll
    for (int j = 0; j < 8; j++) bv[j] = bias[tx * 8 + j];

#pragma unroll
    for (int i = 0; i < 8; i++) {
        int gr = row0 + ty * 8 + i;
        if (gr >= N) continue;
        float r[8];
#pragma unroll
        for (int j = 0; j < 8; j++) {
            unsigned long long p = acc2[i >> 1][j];
            unsigned u = (i & 1) ? (unsigned)(p >> 32) : (unsigned)(p & 0xffffffffu);
            r[j] = __uint_as_float(u) + bv[j];
        }
        float* op = out + (size_t)gr * DD + tx * 8;
        *(float4*)(op)     = make_float4(r[0], r[1], r[2], r[3]);
        *(float4*)(op + 4) = make_float4(r[4], r[5], r[6], r[7]);
    }
}

// ============================================================
// Edge scatter: one warp per 4 edges (MLP=4). Lane l handles
// floats [4l,4l+4) of each edge's 128-float message.
// msg = (type==0 ? Xd : Xc)[src]; agg[dst] += msg via red.global.add.v4.f32
// ============================================================
__global__ __launch_bounds__(256) void edge_kernel(
    const int* __restrict__ ei, const int* __restrict__ et,
    int E, int agg_sel)
{
    int warp = blockIdx.x * 8 + (threadIdx.x >> 5);
    int lane = threadIdx.x & 31;
    int e0 = warp * 4;
    if (e0 >= E) return;

    float* agg = (agg_sel == 0) ? g_aggA : g_aggB;

    int src[4], dst[4], t[4];
    int ne = (E - e0 < 4) ? (E - e0) : 4;
#pragma unroll
    for (int q = 0; q < 4; q++) {
        int e = e0 + ((q < ne) ? q : 0);
        src[q] = __ldg(ei + e);
        dst[q] = __ldg(ei + E + e);
        t[q]   = __ldg(et + e);
    }

    // issue all gathers first (4 outstanding LDG.128 per thread)
    float4 v[4];
#pragma unroll
    for (int q = 0; q < 4; q++) {
        const float* base = (t[q] == 0) ? g_Xd : g_Xc;
        v[q] = *(const float4*)(base + (size_t)src[q] * DD + lane * 4);
    }

#pragma unroll
    for (int q = 0; q < 4; q++) {
        if (q >= ne) break;
        float* dp = agg + (size_t)dst[q] * DD + lane * 4;
        asm volatile("red.global.add.v4.f32 [%0], {%1,%2,%3,%4};"
                     :: "l"(dp), "f"(v[q].x), "f"(v[q].y), "f"(v[q].z), "f"(v[q].w)
                     : "memory");
    }
}

// ============================================================
// Pooling
// ============================================================
__global__ void zero_kernel(float* __restrict__ out, int out_size, int G)
{
    int i = blockIdx.x * blockDim.x + threadIdx.x;
    if (i < out_size) out[i] = 0.f;
    if (i < G) g_cnt[i] = 0.f;
}

// one warp per node: relu(final agg) accumulated into out[batch_id]
__global__ __launch_bounds__(256) void pool_accum_kernel(
    const int* __restrict__ batch_ids, float* __restrict__ out,
    int N, int agg_sel)
{
    int node = blockIdx.x * 8 + (threadIdx.x >> 5);
    int lane = threadIdx.x & 31;
    if (node >= N) return;

    int b = batch_ids[node];
    const float* agg = (agg_sel == 0) ? g_aggA : g_aggB;
    const float* sp = agg + (size_t)node * DD + lane * 4;
    float4 v = *(const float4*)sp;
    v.x = fmaxf(v.x, 0.f); v.y = fmaxf(v.y, 0.f);
    v.z = fmaxf(v.z, 0.f); v.w = fmaxf(v.w, 0.f);

    float* dp = out + (size_t)b * DD + lane * 4;
    asm volatile("red.global.add.v4.f32 [%0], {%1,%2,%3,%4};"
                 :: "l"(dp), "f"(v.x), "f"(v.y), "f"(v.z), "f"(v.w)
                 : "memory");
    if (lane == 0)
        atomicAdd(&g_cnt[b], 1.0f);
}

__global__ void pool_div_kernel(float* __restrict__ out, int out_size)
{
    int i = blockIdx.x * blockDim.x + threadIdx.x;
    if (i >= out_size) return;
    out[i] = out[i] / fmaxf(g_cnt[i >> 7], 1.0f);
}

// ============================================================
// launch
// ============================================================
extern "C" void kernel_launch(void* const* d_in, const int* in_sizes, int n_in,
                              void* d_out, int out_size)
{
    const float* X   = (const float*)d_in[0];
    const float* Wd  = (const float*)d_in[1];
    const float* bd  = (const float*)d_in[2];
    const float* Wc  = (const float*)d_in[3];
    const float* bc  = (const float*)d_in[4];
    const float* Ws  = (const float*)d_in[5];
    const float* bs  = (const float*)d_in[6];
    const int*   ei  = (const int*)d_in[7];
    const int*   et  = (const int*)d_in[8];
    const int*   bid = (const int*)d_in[9];
    float* out = (float*)d_out;

    const int N = in_sizes[0] / DD;
    const int E = in_sizes[8];
    const int G = out_size / DD;

    dim3 ggrid((N + 127) / 128, 3);
    int eblocks = (E + 31) / 32;     // 8 warps/block * 4 edges/warp
    int nblocks = (N + 7) / 8;

    // layer 0: input X (no relu) -> Xd/Xc, self-term -> aggA; edges add into aggA
    gemm3_kernel<<<ggrid, 256>>>(X, 0, 0, Wd, bd, Wc, bc, Ws, bs, 0, 0, N);
    edge_kernel<<<eblocks, 256>>>(ei, et, E, 0);

    // layer 1: input relu(aggA) -> Xd/Xc, self-term -> aggB; edges add into aggB
    gemm3_kernel<<<ggrid, 256>>>(X, 1, 1, Wd, bd, Wc, bc, Ws, bs, 1, 1, N);
    edge_kernel<<<eblocks, 256>>>(ei, et, E, 1);

    // layer 2: input relu(aggB) -> Xd/Xc, self-term -> aggA; edges add into aggA
    gemm3_kernel<<<ggrid, 256>>>(X, 2, 1, Wd, bd, Wc, bc, Ws, bs, 2, 0, N);
    edge_kernel<<<eblocks, 256>>>(ei, et, E, 0);

    // pool: mean over relu(aggA) per graph
    zero_kernel<<<(out_size + G + 255) / 256, 256>>>(out, out_size, G);
    pool_accum_kernel<<<nblocks, 256>>>(bid, out, N, 0);
    pool_div_kernel<<<(out_size + 255) / 256, 256>>>(out, out_size);
}

// round 3
// speedup vs baseline: 1.5651x; 1.3342x over previous
#include <cuda_runtime.h>
#include <cstdint>

#define DD 128
#define NPAD 50048            // covers N=50000
#define GMAXC 64
#define EMAX 1600000

// ---- scratch (device globals; no allocation allowed) ----
__device__ float g_Xd  [(size_t)NPAD * DD];
__device__ float g_Xc  [(size_t)NPAD * DD];
__device__ float g_self[(size_t)NPAD * DD];
__device__ float g_bufA[(size_t)NPAD * DD];
__device__ float g_bufB[(size_t)NPAD * DD];
__device__ float g_cnt[GMAXC];

// CSR scratch
__device__ int g_deg [NPAD + 1];
__device__ int g_off [NPAD + 1];
__device__ int g_cur [NPAD];
__device__ int g_adj [EMAX];          // packed: src | (type<<31)
__device__ int g_bsum[256];

// packed fp32x2 FMA (Blackwell): d = a*b + d, two lanes per instruction
#define FMA_F32X2(d, a, b) \
    asm("fma.rn.f32x2 %0, %1, %2, %0;" : "+l"(d) : "l"(a), "l"(b))
#define SPLAT2(out, x) \
    asm("mov.b64 %0, {%1, %1};" : "=l"(out) : "f"(x))

// ============================================================
// GEMM: {Xd,Xc,self} = Xin @ W*[layer] + b*[layer]
// blockIdx.y selects family. Input already ReLU'd (agg applies it).
// ============================================================
__global__ __launch_bounds__(256) void gemm3_kernel(
    const float* __restrict__ Xext, int in_sel,
    const float* __restrict__ Wd, const float* __restrict__ bd,
    const float* __restrict__ Wc, const float* __restrict__ bc,
    const float* __restrict__ Ws, const float* __restrict__ bs,
    int layer, int N)
{
    const float* Xin = (in_sel == 0) ? Xext : (in_sel == 1 ? g_bufA : g_bufB);
    const float* W; const float* bias; float* out;
    if (blockIdx.y == 0)      { W = Wd; bias = bd; out = g_Xd; }
    else if (blockIdx.y == 1) { W = Wc; bias = bc; out = g_Xc; }
    else                      { W = Ws; bias = bs; out = g_self; }
    W    += (size_t)layer * DD * DD;
    bias += layer * DD;

    __shared__ float As[16][132];   // A transposed: As[k][m]
    __shared__ float Bs[16][132];   // Bs[k][n]

    const int tid = threadIdx.x;
    const int tx  = tid & 15;       // col group (8 cols each)
    const int ty  = tid >> 4;       // row group (8 rows each)
    const int row0 = blockIdx.x * 128;

    unsigned long long acc2[4][8];
#pragma unroll
    for (int i = 0; i < 4; i++)
#pragma unroll
        for (int j = 0; j < 8; j++) acc2[i][j] = 0ull;

    for (int k0 = 0; k0 < DD; k0 += 16) {
#pragma unroll
        for (int q = 0; q < 2; q++) {
            int f = tid * 2 + q;
            int r = f >> 2;
            int c = (f & 3) << 2;
            int gr = row0 + r;
            float4 v = make_float4(0.f, 0.f, 0.f, 0.f);
            if (gr < N)
                v = *(const float4*)(Xin + (size_t)gr * DD + k0 + c);
            As[c + 0][r] = v.x; As[c + 1][r] = v.y;
            As[c + 2][r] = v.z; As[c + 3][r] = v.w;
        }
#pragma unroll
        for (int q = 0; q < 2; q++) {
            int f = tid * 2 + q;
            int r = f >> 5;
            int c = (f & 31) << 2;
            float4 v = *(const float4*)(W + (size_t)(k0 + r) * DD + c);
            Bs[r][c + 0] = v.x; Bs[r][c + 1] = v.y;
            Bs[r][c + 2] = v.z; Bs[r][c + 3] = v.w;
        }
        __syncthreads();

#pragma unroll
        for (int kk = 0; kk < 16; kk++) {
            ulonglong2 a01 = *(const ulonglong2*)&As[kk][ty * 8];
            ulonglong2 a23 = *(const ulonglong2*)&As[kk][ty * 8 + 4];
            unsigned long long a2[4] = {a01.x, a01.y, a23.x, a23.y};
            float4 bA = *(const float4*)&Bs[kk][tx * 8];
            float4 bB = *(const float4*)&Bs[kk][tx * 8 + 4];
            unsigned long long b2[8];
            SPLAT2(b2[0], bA.x); SPLAT2(b2[1], bA.y);
            SPLAT2(b2[2], bA.z); SPLAT2(b2[3], bA.w);
            SPLAT2(b2[4], bB.x); SPLAT2(b2[5], bB.y);
            SPLAT2(b2[6], bB.z); SPLAT2(b2[7], bB.w);
#pragma unroll
            for (int i = 0; i < 4; i++)
#pragma unroll
                for (int j = 0; j < 8; j++)
                    FMA_F32X2(acc2[i][j], a2[i], b2[j]);
        }
        __syncthreads();
    }

    float bv[8];
#pragma unroll
    for (int j = 0; j < 8; j++) bv[j] = bias[tx * 8 + j];

#pragma unroll
    for (int i = 0; i < 8; i++) {
        int gr = row0 + ty * 8 + i;
        if (gr >= N) continue;
        float r[8];
#pragma unroll
        for (int j = 0; j < 8; j++) {
            unsigned long long p = acc2[i >> 1][j];
            unsigned u = (i & 1) ? (unsigned)(p >> 32) : (unsigned)(p & 0xffffffffu);
            r[j] = __uint_as_float(u) + bv[j];
        }
        float* op = out + (size_t)gr * DD + tx * 8;
        *(float4*)(op)     = make_float4(r[0], r[1], r[2], r[3]);
        *(float4*)(op + 4) = make_float4(r[4], r[5], r[6], r[7]);
    }
}

// ============================================================
// CSR build
// ============================================================
__global__ void zero_deg_kernel(int N)
{
    int i = blockIdx.x * blockDim.x + threadIdx.x;
    if (i <= N) g_deg[i] = 0;
}

__global__ void hist_kernel(const int* __restrict__ ei, int E)
{
    int e = blockIdx.x * blockDim.x + threadIdx.x;
    if (e < E) atomicAdd(&g_deg[ei[E + e]], 1);
}

__global__ void scan1_kernel(int N)
{
    __shared__ int s[256];
    int tid = threadIdx.x;
    int i = blockIdx.x * 256 + tid;
    int v = (i < N) ? g_deg[i] : 0;
    s[tid] = v;
    __syncthreads();
#pragma unroll
    for (int o = 1; o < 256; o <<= 1) {
        int t = (tid >= o) ? s[tid - o] : 0;
        __syncthreads();
        s[tid] += t;
        __syncthreads();
    }
    if (i < N) g_off[i] = s[tid] - v;     // exclusive within block
    if (tid == 255) g_bsum[blockIdx.x] = s[255];
}

__global__ void scan2_kernel(int nb)
{
    __shared__ int s[256];
    int tid = threadIdx.x;
    int v = (tid < nb) ? g_bsum[tid] : 0;
    s[tid] = v;
    __syncthreads();
#pragma unroll
    for (int o = 1; o < 256; o <<= 1) {
        int t = (tid >= o) ? s[tid - o] : 0;
        __syncthreads();
        s[tid] += t;
        __syncthreads();
    }
    if (tid < nb) g_bsum[tid] = s[tid] - v;  // exclusive block offsets
}

__global__ void scan3_kernel(int N, int E)
{
    int i = blockIdx.x * blockDim.x + threadIdx.x;
    if (i < N) {
        int o = g_off[i] + g_bsum[i >> 8];
        g_off[i] = o;
        g_cur[i] = o;
    }
    if (i == 0) g_off[N] = E;
}

__global__ void scatter_kernel(const int* __restrict__ ei,
                               const int* __restrict__ et, int E)
{
    int e = blockIdx.x * blockDim.x + threadIdx.x;
    if (e >= E) return;
    int src = ei[e];
    int dst = ei[E + e];
    int t   = et[e];
    int pos = atomicAdd(&g_cur[dst], 1);
    g_adj[pos] = src | (t << 31);
}

// ============================================================
// Aggregation (gather-only, no atomics): one warp per dst node.
// out[n] = relu( self[n] + sum_{e in CSR[n]} (type? Xc : Xd)[src_e] )
// ============================================================
__global__ __launch_bounds__(256) void agg_kernel(int N, int out_sel)
{
    int node = blockIdx.x * 8 + (threadIdx.x >> 5);
    int lane = threadIdx.x & 31;
    if (node >= N) return;

    int beg = g_off[node];
    int end = g_off[node + 1];

    float4 acc = *(const float4*)(g_self + (size_t)node * DD + lane * 4);

    for (int base = beg; base < end; base += 32) {
        int cnt = end - base; if (cnt > 32) cnt = 32;
        int idx = (base + lane < end) ? g_adj[base + lane] : 0;
        int q = 0;
        for (; q + 4 <= cnt; q += 4) {
            float4 v[4];
#pragma unroll
            for (int u = 0; u < 4; u++) {
                int p = __shfl_sync(0xffffffffu, idx, q + u);
                const float* bp = (p < 0) ? g_Xc : g_Xd;
                v[u] = *(const float4*)(bp + (size_t)(p & 0x7fffffff) * DD + lane * 4);
            }
#pragma unroll
            for (int u = 0; u < 4; u++) {
                acc.x += v[u].x; acc.y += v[u].y;
                acc.z += v[u].z; acc.w += v[u].w;
            }
        }
        for (; q < cnt; q++) {
            int p = __shfl_sync(0xffffffffu, idx, q);
            const float* bp = (p < 0) ? g_Xc : g_Xd;
            float4 v = *(const float4*)(bp + (size_t)(p & 0x7fffffff) * DD + lane * 4);
            acc.x += v.x; acc.y += v.y; acc.z += v.z; acc.w += v.w;
        }
    }

    acc.x = fmaxf(acc.x, 0.f); acc.y = fmaxf(acc.y, 0.f);
    acc.z = fmaxf(acc.z, 0.f); acc.w = fmaxf(acc.w, 0.f);

    float* out = (out_sel == 0) ? g_bufA : g_bufB;
    *(float4*)(out + (size_t)node * DD + lane * 4) = acc;
}

// ============================================================
// Pooling
// ============================================================
__global__ void zero_kernel(float* __restrict__ out, int out_size, int G)
{
    int i = blockIdx.x * blockDim.x + threadIdx.x;
    if (i < out_size) out[i] = 0.f;
    if (i < G) g_cnt[i] = 0.f;
}

__global__ __launch_bounds__(256) void pool_accum_kernel(
    const int* __restrict__ batch_ids, float* __restrict__ out, int N)
{
    int node = blockIdx.x * 8 + (threadIdx.x >> 5);
    int lane = threadIdx.x & 31;
    if (node >= N) return;

    int b = batch_ids[node];
    const float* sp = g_bufA + (size_t)node * DD + lane * 4;
    float4 v = *(const float4*)sp;

    float* dp = out + (size_t)b * DD + lane * 4;
    asm volatile("red.global.add.v4.f32 [%0], {%1,%2,%3,%4};"
                 :: "l"(dp), "f"(v.x), "f"(v.y), "f"(v.z), "f"(v.w)
                 : "memory");
    if (lane == 0)
        atomicAdd(&g_cnt[b], 1.0f);
}

__global__ void pool_div_kernel(float* __restrict__ out, int out_size)
{
    int i = blockIdx.x * blockDim.x + threadIdx.x;
    if (i >= out_size) return;
    out[i] = out[i] / fmaxf(g_cnt[i >> 7], 1.0f);
}

// ============================================================
// launch
// ============================================================
extern "C" void kernel_launch(void* const* d_in, const int* in_sizes, int n_in,
                              void* d_out, int out_size)
{
    const float* X   = (const float*)d_in[0];
    const float* Wd  = (const float*)d_in[1];
    const float* bd  = (const float*)d_in[2];
    const float* Wc  = (const float*)d_in[3];
    const float* bc  = (const float*)d_in[4];
    const float* Ws  = (const float*)d_in[5];
    const float* bs  = (const float*)d_in[6];
    const int*   ei  = (const int*)d_in[7];
    const int*   et  = (const int*)d_in[8];
    const int*   bid = (const int*)d_in[9];
    float* out = (float*)d_out;

    const int N = in_sizes[0] / DD;
    const int E = in_sizes[8];
    const int G = out_size / DD;

    dim3 ggrid((N + 127) / 128, 3);
    int eblk  = (E + 255) / 256;
    int nwarp = (N + 7) / 8;
    int nb    = (N + 255) / 256;

    // ---- CSR build (dst-indexed) ----
    zero_deg_kernel<<<(N + 256) / 256, 256>>>(N);
    hist_kernel<<<eblk, 256>>>(ei, E);
    scan1_kernel<<<nb, 256>>>(N);
    scan2_kernel<<<1, 256>>>(nb);
    scan3_kernel<<<nb, 256>>>(N, E);
    scatter_kernel<<<eblk, 256>>>(ei, et, E);

    // ---- layers ----
    gemm3_kernel<<<ggrid, 256>>>(X, 0, Wd, bd, Wc, bc, Ws, bs, 0, N);
    agg_kernel<<<nwarp, 256>>>(N, 0);                 // -> bufA (relu applied)

    gemm3_kernel<<<ggrid, 256>>>(X, 1, Wd, bd, Wc, bc, Ws, bs, 1, N);
    agg_kernel<<<nwarp, 256>>>(N, 1);                 // -> bufB

    gemm3_kernel<<<ggrid, 256>>>(X, 2, Wd, bd, Wc, bc, Ws, bs, 2, N);
    agg_kernel<<<nwarp, 256>>>(N, 0);                 // -> bufA

    // ---- pool: mean over bufA per graph ----
    zero_kernel<<<(out_size + G + 255) / 256, 256>>>(out, out_size, G);
    pool_accum_kernel<<<nwarp, 256>>>(bid, out, N);
    pool_div_kernel<<<(out_size + 255) / 256, 256>>>(out, out_size);
}

// round 5
// speedup vs baseline: 2.0969x; 1.3398x over previous
#include <cuda_runtime.h>
#include <cuda_bf16.h>
#include <cstdint>
#include <cstring>

#define DD 128
#define NPAD 50048
#define GMAXC 64
#define EMAX 1600000
#define SA 136                 // smem row stride in halves (conflict-free, 16B-aligned rows)

// ---- scratch (device globals; no allocation allowed) ----
__device__ float g_Xd  [(size_t)NPAD * DD];
__device__ float g_Xc  [(size_t)NPAD * DD];
__device__ float g_self[(size_t)NPAD * DD];
__device__ float g_bufA[(size_t)NPAD * DD];
__device__ float g_bufB[(size_t)NPAD * DD];
__device__ float g_cnt[GMAXC];

// CSR scratch
__device__ int g_deg [NPAD + 1];
__device__ int g_off [NPAD + 1];
__device__ int g_cur [NPAD];
__device__ int g_adj [EMAX];          // packed: src | (type<<31)
__device__ int g_bsum[256];

// bf16-split weight images, TRANSPOSED [n][k], packed as u32 (k, k+1) pairs
// index = layer*3 + family (0=Wd,1=Wc,2=Ws); each 128x64 u32 = 32KB
__device__ uint32_t g_Wh[9][8192];
__device__ uint32_t g_Wl[9][8192];

// ============================================================
// Weight prep: split W into bf16 hi/lo, transposed to [n][k]
// ============================================================
__global__ void prep_w_kernel(const float* __restrict__ Wd,
                              const float* __restrict__ Wc,
                              const float* __restrict__ Ws)
{
    int img = blockIdx.x;                 // 0..8
    int layer = img / 3, f = img % 3;
    const float* W = ((f == 0) ? Wd : (f == 1) ? Wc : Ws) + (size_t)layer * DD * DD;
    int n = threadIdx.x;                  // output col (row of transposed image)

    uint32_t* Hi = g_Wh[img];
    uint32_t* Lo = g_Wl[img];

    for (int k = 0; k < DD; k += 2) {
        float x0 = W[(size_t)k * DD + n];
        float x1 = W[(size_t)(k + 1) * DD + n];
        __nv_bfloat162 h = __floats2bfloat162_rn(x0, x1);
        float2 hf = __bfloat1622float2(h);
        __nv_bfloat162 l = __floats2bfloat162_rn(x0 - hf.x, x1 - hf.y);
        uint32_t hp, lp;
        memcpy(&hp, &h, 4); memcpy(&lp, &l, 4);
        Hi[n * 64 + (k >> 1)] = hp;
        Lo[n * 64 + (k >> 1)] = lp;
    }
}

// ============================================================
// mma.sync bf16 GEMM: {Xd, Xc, self} = Xin @ W*[layer] + b*
// One CTA per 128-row tile, 8 warps (warp m-tile = 16 rows).
// A split hi/lo in smem (reused by all 3 families), B per family.
// ============================================================
#define MMA_BF16(c, a0, a1, a2, a3, b0, b1)                                    \
    asm volatile("mma.sync.aligned.m16n8k16.row.col.f32.bf16.bf16.f32 "        \
                 "{%0,%1,%2,%3}, {%4,%5,%6,%7}, {%8,%9}, {%0,%1,%2,%3};"       \
                 : "+f"(c[0]), "+f"(c[1]), "+f"(c[2]), "+f"(c[3])              \
                 : "r"(a0), "r"(a1), "r"(a2), "r"(a3), "r"(b0), "r"(b1))

// smem layout (bytes): bias 1536 | Ah 34816 | Al 34816 | Bh 34816 | Bl 34816
#define SM_BIAS 0
#define SM_AH   1536
#define SM_AL   (SM_AH + 128 * SA * 2)
#define SM_BH   (SM_AL + 128 * SA * 2)
#define SM_BL   (SM_BH + 128 * SA * 2)
#define SM_GTOT (SM_BL + 128 * SA * 2)   // 140800

__global__ __launch_bounds__(256, 1) void gemm_mma_kernel(
    const float* __restrict__ Xext, int in_sel, int layer,
    const float* __restrict__ bd, const float* __restrict__ bc,
    const float* __restrict__ bs, int N)
{
    extern __shared__ char smem[];
    float* bias_s = (float*)(smem + SM_BIAS);
    __nv_bfloat16* Ah = (__nv_bfloat16*)(smem + SM_AH);
    __nv_bfloat16* Al = (__nv_bfloat16*)(smem + SM_AL);
    __nv_bfloat16* Bh = (__nv_bfloat16*)(smem + SM_BH);
    __nv_bfloat16* Bl = (__nv_bfloat16*)(smem + SM_BL);

    const int tid = threadIdx.x, wid = tid >> 5, lane = tid & 31;
    const float* Xin = (in_sel == 0) ? Xext : ((in_sel == 1) ? g_bufA : g_bufB);
    const int row0 = blockIdx.x * 128;

    if (tid < 128) {
        bias_s[tid]       = bd[layer * DD + tid];
        bias_s[128 + tid] = bc[layer * DD + tid];
        bias_s[256 + tid] = bs[layer * DD + tid];
    }

    // ---- A conversion: fp32 -> bf16 hi/lo, row-major stride SA ----
    {
        int r  = tid >> 1;
        int c0 = (tid & 1) * 64;
        int gr = row0 + r;
        bool ok = gr < N;
        const float4* xp = (const float4*)(Xin + (size_t)gr * DD + c0);
        uint32_t* ah = (uint32_t*)&Ah[r * SA + c0];
        uint32_t* al = (uint32_t*)&Al[r * SA + c0];
#pragma unroll
        for (int c4 = 0; c4 < 16; c4++) {
            float4 v = ok ? __ldg(xp + c4) : make_float4(0.f, 0.f, 0.f, 0.f);
            __nv_bfloat162 h01 = __floats2bfloat162_rn(v.x, v.y);
            __nv_bfloat162 h23 = __floats2bfloat162_rn(v.z, v.w);
            float2 f01 = __bfloat1622float2(h01);
            float2 f23 = __bfloat1622float2(h23);
            __nv_bfloat162 l01 = __floats2bfloat162_rn(v.x - f01.x, v.y - f01.y);
            __nv_bfloat162 l23 = __floats2bfloat162_rn(v.z - f23.x, v.w - f23.y);
            uint32_t hp0, hp1, lp0, lp1;
            memcpy(&hp0, &h01, 4); memcpy(&hp1, &h23, 4);
            memcpy(&lp0, &l01, 4); memcpy(&lp1, &l23, 4);
            ah[c4 * 2] = hp0; ah[c4 * 2 + 1] = hp1;
            al[c4 * 2] = lp0; al[c4 * 2 + 1] = lp1;
        }
    }

    const int mrow = wid * 16;
    const int r    = lane >> 2;           // quad row 0..7
    const int cc   = (lane & 3) * 2;      // element pair within k/n group

    for (int f = 0; f < 3; f++) {
        __syncthreads();                  // A ready (f=0) / B buffer free (f>0)
        // copy family B images (hi+lo) into smem, re-strided to SA
        {
            const uint4* sh = (const uint4*)g_Wh[layer * 3 + f];
            const uint4* sl = (const uint4*)g_Wl[layer * 3 + f];
            for (int i = tid; i < 2048; i += 256) {
                int rr = i >> 4, c16 = i & 15;
                *(uint4*)&Bh[rr * SA + c16 * 8] = sh[i];
                *(uint4*)&Bl[rr * SA + c16 * 8] = sl[i];
            }
        }
        __syncthreads();

        float acc[16][4];
#pragma unroll
        for (int nt = 0; nt < 16; nt++)
#pragma unroll
            for (int q = 0; q < 4; q++) acc[nt][q] = 0.f;

#pragma unroll
        for (int ks = 0; ks < 8; ks++) {
            const int kb = ks * 16;
            uint32_t a0h = *(const uint32_t*)&Ah[(mrow + r)     * SA + kb + cc];
            uint32_t a1h = *(const uint32_t*)&Ah[(mrow + r + 8) * SA + kb + cc];
            uint32_t a2h = *(const uint32_t*)&Ah[(mrow + r)     * SA + kb + cc + 8];
            uint32_t a3h = *(const uint32_t*)&Ah[(mrow + r + 8) * SA + kb + cc + 8];
            uint32_t a0l = *(const uint32_t*)&Al[(mrow + r)     * SA + kb + cc];
            uint32_t a1l = *(const uint32_t*)&Al[(mrow + r + 8) * SA + kb + cc];
            uint32_t a2l = *(const uint32_t*)&Al[(mrow + r)     * SA + kb + cc + 8];
            uint32_t a3l = *(const uint32_t*)&Al[(mrow + r + 8) * SA + kb + cc + 8];
#pragma unroll
            for (int nt = 0; nt < 16; nt++) {
                const int nb = (nt * 8 + r) * SA + kb + cc;
                uint32_t b0h = *(const uint32_t*)&Bh[nb];
                uint32_t b1h = *(const uint32_t*)&Bh[nb + 8];
                uint32_t b0l = *(const uint32_t*)&Bl[nb];
                uint32_t b1l = *(const uint32_t*)&Bl[nb + 8];
                MMA_BF16(acc[nt], a0h, a1h, a2h, a3h, b0h, b1h);
                MMA_BF16(acc[nt], a0h, a1h, a2h, a3h, b0l, b1l);
                MMA_BF16(acc[nt], a0l, a1l, a2l, a3l, b0h, b1h);
            }
        }

        // epilogue: +bias, float2 stores (C frag: rows r, r+8; cols cc, cc+1)
        float* out = (f == 0) ? g_Xd : ((f == 1) ? g_Xc : g_self);
        const float* bv = bias_s + f * 128;
        int gr0 = row0 + mrow + r;
        int gr1 = gr0 + 8;
#pragma unroll
        for (int nt = 0; nt < 16; nt++) {
            int col = nt * 8 + cc;
            float bx = bv[col], by = bv[col + 1];
            if (gr0 < N)
                *(float2*)(out + (size_t)gr0 * DD + col) =
                    make_float2(acc[nt][0] + bx, acc[nt][1] + by);
            if (gr1 < N)
                *(float2*)(out + (size_t)gr1 * DD + col) =
                    make_float2(acc[nt][2] + bx, acc[nt][3] + by);
        }
    }
}

// ============================================================
// CSR build
// ============================================================
__global__ void zero_deg_kernel(int N)
{
    int i = blockIdx.x * blockDim.x + threadIdx.x;
    if (i <= N) g_deg[i] = 0;
}

__global__ void hist_kernel(const int* __restrict__ ei, int E)
{
    int e = blockIdx.x * blockDim.x + threadIdx.x;
    if (e < E) atomicAdd(&g_deg[ei[E + e]], 1);
}

__global__ void scan1_kernel(int N)
{
    __shared__ int s[256];
    int tid = threadIdx.x;
    int i = blockIdx.x * 256 + tid;
    int v = (i < N) ? g_deg[i] : 0;
    s[tid] = v;
    __syncthreads();
#pragma unroll
    for (int o = 1; o < 256; o <<= 1) {
        int t = (tid >= o) ? s[tid - o] : 0;
        __syncthreads();
        s[tid] += t;
        __syncthreads();
    }
    if (i < N) g_off[i] = s[tid] - v;
    if (tid == 255) g_bsum[blockIdx.x] = s[255];
}

__global__ void scan2_kernel(int nb)
{
    __shared__ int s[256];
    int tid = threadIdx.x;
    int v = (tid < nb) ? g_bsum[tid] : 0;
    s[tid] = v;
    __syncthreads();
#pragma unroll
    for (int o = 1; o < 256; o <<= 1) {
        int t = (tid >= o) ? s[tid - o] : 0;
        __syncthreads();
        s[tid] += t;
        __syncthreads();
    }
    if (tid < nb) g_bsum[tid] = s[tid] - v;
}

__global__ void scan3_kernel(int N, int E)
{
    int i = blockIdx.x * blockDim.x + threadIdx.x;
    if (i < N) {
        int o = g_off[i] + g_bsum[i >> 8];
        g_off[i] = o;
        g_cur[i] = o;
    }
    if (i == 0) g_off[N] = E;
}

__global__ void scatter_kernel(const int* __restrict__ ei,
                               const int* __restrict__ et, int E)
{
    int e = blockIdx.x * blockDim.x + threadIdx.x;
    if (e >= E) return;
    int src = ei[e];
    int dst = ei[E + e];
    int t   = et[e];
    int pos = atomicAdd(&g_cur[dst], 1);
    g_adj[pos] = src | (t << 31);
}

// ============================================================
// Aggregation (gather-only): one warp per dst node.
// out[n] = relu( self[n] + sum_{e in CSR[n]} (type? Xc : Xd)[src_e] )
// ============================================================
__global__ __launch_bounds__(256) void agg_kernel(int N, int out_sel)
{
    int node = blockIdx.x * 8 + (threadIdx.x >> 5);
    int lane = threadIdx.x & 31;
    if (node >= N) return;

    int beg = g_off[node];
    int end = g_off[node + 1];

    float4 acc = *(const float4*)(g_self + (size_t)node * DD + lane * 4);

    for (int base = beg; base < end; base += 32) {
        int cnt = end - base; if (cnt > 32) cnt = 32;
        int idx = (base + lane < end) ? g_adj[base + lane] : 0;
        int q = 0;
        for (; q + 4 <= cnt; q += 4) {
            float4 v[4];
#pragma unroll
            for (int u = 0; u < 4; u++) {
                int p = __shfl_sync(0xffffffffu, idx, q + u);
                const float* bp = (p < 0) ? g_Xc : g_Xd;
                v[u] = *(const float4*)(bp + (size_t)(p & 0x7fffffff) * DD + lane * 4);
            }
#pragma unroll
            for (int u = 0; u < 4; u++) {
                acc.x += v[u].x; acc.y += v[u].y;
                acc.z += v[u].z; acc.w += v[u].w;
            }
        }
        for (; q < cnt; q++) {
            int p = __shfl_sync(0xffffffffu, idx, q);
            const float* bp = (p < 0) ? g_Xc : g_Xd;
            float4 v = *(const float4*)(bp + (size_t)(p & 0x7fffffff) * DD + lane * 4);
            acc.x += v.x; acc.y += v.y; acc.z += v.z; acc.w += v.w;
        }
    }

    acc.x = fmaxf(acc.x, 0.f); acc.y = fmaxf(acc.y, 0.f);
    acc.z = fmaxf(acc.z, 0.f); acc.w = fmaxf(acc.w, 0.f);

    float* out = (out_sel == 0) ? g_bufA : g_bufB;
    *(float4*)(out + (size_t)node * DD + lane * 4) = acc;
}

// ============================================================
// Pooling
// ============================================================
__global__ void zero_kernel(float* __restrict__ out, int out_size, int G)
{
    int i = blockIdx.x * blockDim.x + threadIdx.x;
    if (i < out_size) out[i] = 0.f;
    if (i < G) g_cnt[i] = 0.f;
}

__global__ __launch_bounds__(256) void pool_accum_kernel(
    const int* __restrict__ batch_ids, float* __restrict__ out, int N)
{
    int node = blockIdx.x * 8 + (threadIdx.x >> 5);
    int lane = threadIdx.x & 31;
    if (node >= N) return;

    int b = batch_ids[node];
    const float* sp = g_bufA + (size_t)node * DD + lane * 4;
    float4 v = *(const float4*)sp;

    float* dp = out + (size_t)b * DD + lane * 4;
    asm volatile("red.global.add.v4.f32 [%0], {%1,%2,%3,%4};"
                 :: "l"(dp), "f"(v.x), "f"(v.y), "f"(v.z), "f"(v.w)
                 : "memory");
    if (lane == 0)
        atomicAdd(&g_cnt[b], 1.0f);
}

__global__ void pool_div_kernel(float* __restrict__ out, int out_size)
{
    int i = blockIdx.x * blockDim.x + threadIdx.x;
    if (i >= out_size) return;
    out[i] = out[i] / fmaxf(g_cnt[i >> 7], 1.0f);
}

// ============================================================
// launch
// ============================================================
extern "C" void kernel_launch(void* const* d_in, const int* in_sizes, int n_in,
                              void* d_out, int out_size)
{
    const float* X   = (const float*)d_in[0];
    const float* Wd  = (const float*)d_in[1];
    const float* bd  = (const float*)d_in[2];
    const float* Wc  = (const float*)d_in[3];
    const float* bc  = (const float*)d_in[4];
    const float* Ws  = (const float*)d_in[5];
    const float* bs  = (const float*)d_in[6];
    const int*   ei  = (const int*)d_in[7];
    const int*   et  = (const int*)d_in[8];
    const int*   bid = (const int*)d_in[9];
    float* out = (float*)d_out;

    const int N = in_sizes[0] / DD;
    const int E = in_sizes[8];
    const int G = out_size / DD;

    static bool attr_done = false;
    if (!attr_done) {
        cudaFuncSetAttribute(gemm_mma_kernel,
                             cudaFuncAttributeMaxDynamicSharedMemorySize, SM_GTOT);
        attr_done = true;
    }

    int gtiles = (N + 127) / 128;
    int eblk  = (E + 255) / 256;
    int nwarp = (N + 7) / 8;
    int nb    = (N + 255) / 256;

    // ---- weight prep + CSR build ----
    prep_w_kernel<<<9, 128>>>(Wd, Wc, Ws);
    zero_deg_kernel<<<(N + 256) / 256, 256>>>(N);
    hist_kernel<<<eblk, 256>>>(ei, E);
    scan1_kernel<<<nb, 256>>>(N);
    scan2_kernel<<<1, 256>>>(nb);
    scan3_kernel<<<nb, 256>>>(N, E);
    scatter_kernel<<<eblk, 256>>>(ei, et, E);

    // ---- layers ----
    gemm_mma_kernel<<<gtiles, 256, SM_GTOT>>>(X, 0, 0, bd, bc, bs, N);
    agg_kernel<<<nwarp, 256>>>(N, 0);                 // -> bufA (relu applied)

    gemm_mma_kernel<<<gtiles, 256, SM_GTOT>>>(X, 1, 1, bd, bc, bs, N);
    agg_kernel<<<nwarp, 256>>>(N, 1);                 // -> bufB

    gemm_mma_kernel<<<gtiles, 256, SM_GTOT>>>(X, 2, 2, bd, bc, bs, N);
    agg_kernel<<<nwarp, 256>>>(N, 0);                 // -> bufA

    // ---- pool: mean over bufA per graph ----
    zero_kernel<<<(out_size + G + 255) / 256, 256>>>(out, out_size, G);
    pool_accum_kernel<<<nwarp, 256>>>(bid, out, N);
    pool_div_kernel<<<(out_size + 255) / 256, 256>>>(out, out_size);
}